// round 5
// baseline (speedup 1.0000x reference)
#include <cuda_runtime.h>

#define STRIP_W 128
#define STRIP_R 32            // output rows per warp
#define NTHREADS 256          // 8 warps * 32 rows = 256 rows = full plane height

__global__ __launch_bounds__(NTHREADS)
void conv3x3_v5(const float* __restrict__ X,
                const float* __restrict__ Kp,
                float* __restrict__ O,
                int H, int W)
{
    const int bc = blockIdx.z;
    const int x0 = blockIdx.x * STRIP_W;

    const float* __restrict__ Xp = X + (size_t)bc * H * W;
    float* __restrict__ Op       = O + (size_t)bc * H * W;

    const float k00 = __ldg(&Kp[0]), k01 = __ldg(&Kp[1]), k02 = __ldg(&Kp[2]);
    const float k10 = __ldg(&Kp[3]), k11 = __ldg(&Kp[4]), k12 = __ldg(&Kp[5]);
    const float k20 = __ldg(&Kp[6]), k21 = __ldg(&Kp[7]), k22 = __ldg(&Kp[8]);

    const int tid  = threadIdx.x;
    const int warp = tid >> 5;
    const int lane = tid & 31;
    const int y0   = warp * STRIP_R;

    const int W4g   = W >> 2;                 // 64
    const int base4 = (x0 >> 2) + lane;
    const float4* __restrict__ Xp4 = (const float4*)Xp;
    float4* __restrict__ Op4       = (float4*)Op;

    // Only the lane that USES the halo loads it, as a scalar.
    const bool do_l = (lane == 0)  && (x0 > 0);
    const bool do_r = (lane == 31) && (x0 + STRIP_W < W);

    const float4 Z = make_float4(0.f, 0.f, 0.f, 0.f);

    // row loader: float4 interior + predicated scalar edge halos
    auto load_row = [&](int t, float4& v, float& lh, float& rh) {
        v = Z; lh = 0.f; rh = 0.f;
        if (t >= 0 && t < H) {
            v = Xp4[(size_t)t * W4g + base4];
            if (do_l) lh = Xp[(size_t)t * W + x0 - 1];
            if (do_r) rh = Xp[(size_t)t * W + x0 + STRIP_W];
        }
    };

    // 2-deep pipeline: A = row being consumed, B = row in flight behind it
    float4 vA, vB;  float lhA, rhA, lhB, rhB;
    load_row(y0 - 1, vA, lhA, rhA);
    load_row(y0,     vB, lhB, rhB);

    float4 accP = Z;   // out row t-1 (awaiting kernel row 2)
    float4 accQ = Z;   // out row t+1 partial (kernel row 0)

    #pragma unroll 2
    for (int i = 0; i <= STRIP_R + 1; i++) {
        const int t = y0 - 1 + i;

        // prefetch row t+2 (keeps 2 loads in flight per warp)
        float4 vN = Z;  float lhN = 0.f, rhN = 0.f;
        if (i <= STRIP_R - 1)
            load_row(t + 2, vN, lhN, rhN);

        // horizontal neighbors of current row (vA): unconditional shuffles + selects
        const float up = __shfl_up_sync(0xffffffffu,   vA.w, 1);
        const float dn = __shfl_down_sync(0xffffffffu, vA.x, 1);
        const float L  = (lane == 0)  ? lhA : up;
        const float R  = (lane == 31) ? rhA : dn;

        // out row t-1 completes with kernel row 2 of input row t
        accP.x += k20 * L    + k21 * vA.x + k22 * vA.y;
        accP.y += k20 * vA.x + k21 * vA.y + k22 * vA.z;
        accP.z += k20 * vA.y + k21 * vA.z + k22 * vA.w;
        accP.w += k20 * vA.z + k21 * vA.w + k22 * R;
        if (i >= 2)
            Op4[(size_t)(t - 1) * W4g + base4] = accP;

        // out row t: previous partial + kernel row 1
        accP.x = accQ.x + (k10 * L    + k11 * vA.x + k12 * vA.y);
        accP.y = accQ.y + (k10 * vA.x + k11 * vA.y + k12 * vA.z);
        accP.z = accQ.z + (k10 * vA.y + k11 * vA.z + k12 * vA.w);
        accP.w = accQ.w + (k10 * vA.z + k11 * vA.w + k12 * R);

        // out row t+1: kernel row 0
        accQ.x = k00 * L    + k01 * vA.x + k02 * vA.y;
        accQ.y = k00 * vA.x + k01 * vA.y + k02 * vA.z;
        accQ.z = k00 * vA.y + k01 * vA.z + k02 * vA.w;
        accQ.w = k00 * vA.z + k01 * vA.w + k02 * R;

        // rotate pipeline
        vA = vB; lhA = lhB; rhA = rhB;
        vB = vN; lhB = lhN; rhB = rhN;
    }
}

extern "C" void kernel_launch(void* const* d_in, const int* in_sizes, int n_in,
                              void* d_out, int out_size)
{
    const float* X = (const float*)d_in[0];   // (16, 64, 256, 256) fp32
    const float* K = (const float*)d_in[1];   // (3, 3) fp32
    float* O = (float*)d_out;

    const int H = 256, W = 256;
    const int planes = in_sizes[0] / (H * W); // 1024

    dim3 block(NTHREADS, 1, 1);
    dim3 grid(W / STRIP_W, 1, planes);        // (2, 1, 1024)
    conv3x3_v5<<<grid, block>>>(X, K, O, H, W);
}

// round 6
// speedup vs baseline: 1.1278x; 1.1278x over previous
#include <cuda_runtime.h>

#define NTHREADS 128          // 4 warps per block
#define ROWS_PER_WARP 32      // block covers 128 rows of a plane

__global__ __launch_bounds__(NTHREADS)
void conv3x3_v6(const float* __restrict__ X,
                const float* __restrict__ Kp,
                float* __restrict__ O,
                int H, int W)
{
    const int bc = blockIdx.z;

    const float* __restrict__ Xp = X + (size_t)bc * H * W;
    float* __restrict__ Op       = O + (size_t)bc * H * W;

    const float k00 = __ldg(&Kp[0]), k01 = __ldg(&Kp[1]), k02 = __ldg(&Kp[2]);
    const float k10 = __ldg(&Kp[3]), k11 = __ldg(&Kp[4]), k12 = __ldg(&Kp[5]);
    const float k20 = __ldg(&Kp[6]), k21 = __ldg(&Kp[7]), k22 = __ldg(&Kp[8]);

    const int tid  = threadIdx.x;
    const int warp = tid >> 5;
    const int lane = tid & 31;
    const int y0   = blockIdx.y * (4 * ROWS_PER_WARP) + warp * ROWS_PER_WARP;

    const int W4g = W >> 2;                   // 64 float4 per row
    // lane covers float4 columns `lane` (cols 4l..4l+3) and `lane+32` (cols 128+4l..)
    const float4* __restrict__ Xp4 = (const float4*)Xp;
    float4* __restrict__ Op4       = (float4*)Op;

    const float4 Z = make_float4(0.f, 0.f, 0.f, 0.f);

    auto load_row = [&](int t, float4& lo, float4& hi) {
        lo = Z; hi = Z;
        if (t >= 0 && t < H) {
            const size_t rb = (size_t)t * W4g;
            lo = Xp4[rb + lane];
            hi = Xp4[rb + lane + 32];
        }
    };

    float4 vLo, vHi;
    load_row(y0 - 1, vLo, vHi);

    float4 pLo = Z, pHi = Z;   // out row t-1 (awaiting kernel row 2)
    float4 qLo = Z, qHi = Z;   // out row t+1 partial (kernel row 0)

    #pragma unroll 2
    for (int i = 0; i <= ROWS_PER_WARP + 1; i++) {
        const int t = y0 - 1 + i;

        // prefetch next input row (2 independent LDG.128 in flight)
        float4 nLo = Z, nHi = Z;
        if (i <= ROWS_PER_WARP)
            load_row(t + 1, nLo, nHi);

        // horizontal neighbors: all shuffles unconditional, then value selects
        const float upLo = __shfl_up_sync(0xffffffffu,   vLo.w, 1);
        const float dnLo = __shfl_down_sync(0xffffffffu, vLo.x, 1);
        const float upHi = __shfl_up_sync(0xffffffffu,   vHi.w, 1);
        const float dnHi = __shfl_down_sync(0xffffffffu, vHi.x, 1);
        const float crossL = __shfl_sync(0xffffffffu, vLo.w, 31); // for hi, lane 0
        const float crossR = __shfl_sync(0xffffffffu, vHi.x, 0);  // for lo, lane 31

        const float Llo = (lane == 0)  ? 0.f    : upLo;   // image left edge
        const float Rlo = (lane == 31) ? crossR : dnLo;   // mid boundary
        const float Lhi = (lane == 0)  ? crossL : upHi;   // mid boundary
        const float Rhi = (lane == 31) ? 0.f    : dnHi;   // image right edge

        // ---- out row t-1 completes with kernel row 2 of input row t ----
        pLo.x += k20 * Llo   + k21 * vLo.x + k22 * vLo.y;
        pLo.y += k20 * vLo.x + k21 * vLo.y + k22 * vLo.z;
        pLo.z += k20 * vLo.y + k21 * vLo.z + k22 * vLo.w;
        pLo.w += k20 * vLo.z + k21 * vLo.w + k22 * Rlo;
        pHi.x += k20 * Lhi   + k21 * vHi.x + k22 * vHi.y;
        pHi.y += k20 * vHi.x + k21 * vHi.y + k22 * vHi.z;
        pHi.z += k20 * vHi.y + k21 * vHi.z + k22 * vHi.w;
        pHi.w += k20 * vHi.z + k21 * vHi.w + k22 * Rhi;
        if (i >= 2) {
            const size_t rb = (size_t)(t - 1) * W4g;
            Op4[rb + lane]      = pLo;
            Op4[rb + lane + 32] = pHi;
        }

        // ---- out row t: previous partial + kernel row 1 ----
        pLo.x = qLo.x + (k10 * Llo   + k11 * vLo.x + k12 * vLo.y);
        pLo.y = qLo.y + (k10 * vLo.x + k11 * vLo.y + k12 * vLo.z);
        pLo.z = qLo.z + (k10 * vLo.y + k11 * vLo.z + k12 * vLo.w);
        pLo.w = qLo.w + (k10 * vLo.z + k11 * vLo.w + k12 * Rlo);
        pHi.x = qHi.x + (k10 * Lhi   + k11 * vHi.x + k12 * vHi.y);
        pHi.y = qHi.y + (k10 * vHi.x + k11 * vHi.y + k12 * vHi.z);
        pHi.z = qHi.z + (k10 * vHi.y + k11 * vHi.z + k12 * vHi.w);
        pHi.w = qHi.w + (k10 * vHi.z + k11 * vHi.w + k12 * Rhi);

        // ---- out row t+1: kernel row 0 ----
        qLo.x = k00 * Llo   + k01 * vLo.x + k02 * vLo.y;
        qLo.y = k00 * vLo.x + k01 * vLo.y + k02 * vLo.z;
        qLo.z = k00 * vLo.y + k01 * vLo.z + k02 * vLo.w;
        qLo.w = k00 * vLo.z + k01 * vLo.w + k02 * Rlo;
        qHi.x = k00 * Lhi   + k01 * vHi.x + k02 * vHi.y;
        qHi.y = k00 * vHi.x + k01 * vHi.y + k02 * vHi.z;
        qHi.z = k00 * vHi.y + k01 * vHi.z + k02 * vHi.w;
        qHi.w = k00 * vHi.z + k01 * vHi.w + k02 * Rhi;

        vLo = nLo; vHi = nHi;
    }
}

extern "C" void kernel_launch(void* const* d_in, const int* in_sizes, int n_in,
                              void* d_out, int out_size)
{
    const float* X = (const float*)d_in[0];   // (16, 64, 256, 256) fp32
    const float* K = (const float*)d_in[1];   // (3, 3) fp32
    float* O = (float*)d_out;

    const int H = 256, W = 256;
    const int planes = in_sizes[0] / (H * W); // 1024

    dim3 block(NTHREADS, 1, 1);
    dim3 grid(1, H / (4 * ROWS_PER_WARP), planes);  // (1, 2, 1024) = 2048 blocks
    conv3x3_v6<<<grid, block>>>(X, K, O, H, W);
}

// round 7
// speedup vs baseline: 1.1799x; 1.0462x over previous
#include <cuda_runtime.h>
#include <cstdint>

#define NTH 128               // 4 warps
#define RPW 32                // output rows per warp
#define STAGES 4              // cp.async ring depth (rows in flight per warp)

__device__ __forceinline__ void cp_async16(uint32_t saddr, const void* gptr) {
    asm volatile("cp.async.cg.shared.global [%0], [%1], 16;\n"
                 :: "r"(saddr), "l"(gptr) : "memory");
}
__device__ __forceinline__ void cp_commit() {
    asm volatile("cp.async.commit_group;\n" ::: "memory");
}
template <int N>
__device__ __forceinline__ void cp_wait() {
    asm volatile("cp.async.wait_group %0;\n" :: "n"(N) : "memory");
}

__global__ __launch_bounds__(NTH)
void conv3x3_v7(const float* __restrict__ X,
                const float* __restrict__ Kp,
                float* __restrict__ O,
                int H, int W)
{
    // warp-private ring: [warp][stage][256 floats] (1KB per row)
    __shared__ float buf[4][STAGES][256];

    const int bc = blockIdx.z;
    const float* __restrict__ Xp = X + (size_t)bc * H * W;
    float* __restrict__ Op       = O + (size_t)bc * H * W;

    const float k00 = __ldg(&Kp[0]), k01 = __ldg(&Kp[1]), k02 = __ldg(&Kp[2]);
    const float k10 = __ldg(&Kp[3]), k11 = __ldg(&Kp[4]), k12 = __ldg(&Kp[5]);
    const float k20 = __ldg(&Kp[6]), k21 = __ldg(&Kp[7]), k22 = __ldg(&Kp[8]);

    const int tid  = threadIdx.x;
    const int warp = tid >> 5;
    const int lane = tid & 31;
    const int y0   = blockIdx.y * (4 * RPW) + warp * RPW;

    const int W4g = W >> 2;   // 64
    const float4* __restrict__ Xp4 = (const float4*)Xp;
    float4* __restrict__ Op4       = (float4*)Op;
    const float4 Z = make_float4(0.f, 0.f, 0.f, 0.f);

    // smem addresses for this lane's two 16B chunks, per stage
    float* wbase = &buf[warp][0][0];
    const uint32_t sbase = (uint32_t)__cvta_generic_to_shared(wbase) + lane * 16u;
    // stage s: sbase + s*1024 (+512 for hi chunk)

    // issue row t into stage s; always commits exactly one group
    auto issue_row = [&](int t, int s, bool valid) {
        if (valid && t >= 0 && t < H) {
            const float* g = Xp + (size_t)t * W + lane * 4;
            const uint32_t a = sbase + (uint32_t)s * 1024u;
            cp_async16(a,        g);
            cp_async16(a + 512u, g + 128);
        } else if (valid) {
            float4* d = (float4*)(wbase + s * 256 + lane * 4);
            d[0]  = Z;      // cols [4l..4l+3]
            d[32] = Z;      // cols [128+4l..]
        }
        cp_commit();
    };

    // prologue: rows y0-1 .. y0+2 into stages 0..3
    #pragma unroll
    for (int s = 0; s < STAGES; s++)
        issue_row(y0 - 1 + s, s, true);

    float4 pLo = Z, pHi = Z;   // out row t-1 (awaiting kernel row 2)
    float4 qLo = Z, qHi = Z;   // out row t+1 partial (kernel row 0)

    #pragma unroll 2
    for (int i = 0; i <= RPW + 1; i++) {
        const int t = y0 - 1 + i;
        const int s = i & (STAGES - 1);

        cp_wait<STAGES - 1>();   // oldest group (stage s) complete

        // read this lane's own bytes back (no cross-thread smem reads -> no sync)
        const float4* src = (const float4*)(wbase + s * 256 + lane * 4);
        const float4 vLo = src[0];
        const float4 vHi = src[32];

        // refill stage s with row t+STAGES (only if it will be consumed)
        issue_row(t + STAGES, s, (i + STAGES) <= RPW + 1);

        // horizontal neighbors: unconditional shuffles + value selects
        const float upLo = __shfl_up_sync(0xffffffffu,   vLo.w, 1);
        const float dnLo = __shfl_down_sync(0xffffffffu, vLo.x, 1);
        const float upHi = __shfl_up_sync(0xffffffffu,   vHi.w, 1);
        const float dnHi = __shfl_down_sync(0xffffffffu, vHi.x, 1);
        const float crossL = __shfl_sync(0xffffffffu, vLo.w, 31);
        const float crossR = __shfl_sync(0xffffffffu, vHi.x, 0);

        const float Llo = (lane == 0)  ? 0.f    : upLo;
        const float Rlo = (lane == 31) ? crossR : dnLo;
        const float Lhi = (lane == 0)  ? crossL : upHi;
        const float Rhi = (lane == 31) ? 0.f    : dnHi;

        // out row t-1 completes with kernel row 2 of input row t
        pLo.x += k20 * Llo   + k21 * vLo.x + k22 * vLo.y;
        pLo.y += k20 * vLo.x + k21 * vLo.y + k22 * vLo.z;
        pLo.z += k20 * vLo.y + k21 * vLo.z + k22 * vLo.w;
        pLo.w += k20 * vLo.z + k21 * vLo.w + k22 * Rlo;
        pHi.x += k20 * Lhi   + k21 * vHi.x + k22 * vHi.y;
        pHi.y += k20 * vHi.x + k21 * vHi.y + k22 * vHi.z;
        pHi.z += k20 * vHi.y + k21 * vHi.z + k22 * vHi.w;
        pHi.w += k20 * vHi.z + k21 * vHi.w + k22 * Rhi;
        if (i >= 2) {
            const size_t rb = (size_t)(t - 1) * W4g;
            Op4[rb + lane]      = pLo;
            Op4[rb + lane + 32] = pHi;
        }

        // out row t: previous partial + kernel row 1
        pLo.x = qLo.x + (k10 * Llo   + k11 * vLo.x + k12 * vLo.y);
        pLo.y = qLo.y + (k10 * vLo.x + k11 * vLo.y + k12 * vLo.z);
        pLo.z = qLo.z + (k10 * vLo.y + k11 * vLo.z + k12 * vLo.w);
        pLo.w = qLo.w + (k10 * vLo.z + k11 * vLo.w + k12 * Rlo);
        pHi.x = qHi.x + (k10 * Lhi   + k11 * vHi.x + k12 * vHi.y);
        pHi.y = qHi.y + (k10 * vHi.x + k11 * vHi.y + k12 * vHi.z);
        pHi.z = qHi.z + (k10 * vHi.y + k11 * vHi.z + k12 * vHi.w);
        pHi.w = qHi.w + (k10 * vHi.z + k11 * vHi.w + k12 * Rhi);

        // out row t+1: kernel row 0
        qLo.x = k00 * Llo   + k01 * vLo.x + k02 * vLo.y;
        qLo.y = k00 * vLo.x + k01 * vLo.y + k02 * vLo.z;
        qLo.z = k00 * vLo.y + k01 * vLo.z + k02 * vLo.w;
        qLo.w = k00 * vLo.z + k01 * vLo.w + k02 * Rlo;
        qHi.x = k00 * Lhi   + k01 * vHi.x + k02 * vHi.y;
        qHi.y = k00 * vHi.x + k01 * vHi.y + k02 * vHi.z;
        qHi.z = k00 * vHi.y + k01 * vHi.z + k02 * vHi.w;
        qHi.w = k00 * vHi.z + k01 * vHi.w + k02 * Rhi;
    }
}

extern "C" void kernel_launch(void* const* d_in, const int* in_sizes, int n_in,
                              void* d_out, int out_size)
{
    const float* X = (const float*)d_in[0];   // (16, 64, 256, 256) fp32
    const float* K = (const float*)d_in[1];   // (3, 3) fp32
    float* O = (float*)d_out;

    const int H = 256, W = 256;
    const int planes = in_sizes[0] / (H * W); // 1024

    dim3 block(NTH, 1, 1);
    dim3 grid(1, H / (4 * RPW), planes);      // (1, 2, 1024) = 2048 blocks
    conv3x3_v7<<<grid, block>>>(X, K, O, H, W);
}